// round 11
// baseline (speedup 1.0000x reference)
#include <cuda_runtime.h>
#include <stdint.h>
#include <math.h>

// Problem constants (fixed by dataset)
#define MAXN     100000
#define FIN      128
#define HID      64
#define NBW      ((MAXN + 31) / 32)   // 3125 words = 12.5 KB bitmaps
#define MAXSLOTS 16384                // |V1| bound (actual ~2.1k)
#define MAXL2    65536                // layer-2 edge bound (actual ~2k)
#define MSHIFT   41                   // magic-division shift
#define NB       148                  // persistent blocks (<= SM count)
#define NT       1024                 // threads per block

// ---------------- static device scratch ------------------------------------
// Zero at load; Phase F re-zeroes everything dirtied each call.
__device__ int      d_deg[MAXN];
__device__ unsigned d_isout_bits[NBW];
__device__ unsigned d_need_bits[NBW];
__device__ int      d_slot[MAXN];
__device__ int      d_slotnode[MAXSLOTS];
__device__ __align__(16) float d_xagg[(size_t)MAXSLOTS * FIN];
__device__ float    d_tval[MAXSLOTS];
__device__ float    d_sdinv[MAXSLOTS];
__device__ int2     d_l2[MAXL2];
__device__ int      d_outnodes[MAXSLOTS];
__device__ int      d_nslots;
__device__ int      d_nl2;
__device__ int      d_nout;
__device__ int      d_formula_ok = 1;
// global barrier state (generation barrier; persists harmlessly across calls)
__device__ unsigned          d_bar_count = 0;
__device__ volatile unsigned d_bar_gen   = 0;

__device__ __forceinline__ void red_add_v4(float* addr, float a, float b, float c, float d) {
    asm volatile("red.global.add.v4.f32 [%0], {%1,%2,%3,%4};"
                 :: "l"(addr), "f"(a), "f"(b), "f"(c), "f"(d) : "memory");
}
__device__ __forceinline__ int test_bit(const unsigned* bits, int i) {
    return (bits[i >> 5] >> (i & 31)) & 1u;
}
__device__ __forceinline__ int mdiv(unsigned a, unsigned long long m) {
    return (int)((a * m) >> MSHIFT);   // floor(a/N), exact: a*e < 2^41
}
__device__ __forceinline__ void zero_row(int s) {
    float4* row = (float4*)&d_xagg[(size_t)s * FIN];
    #pragma unroll
    for (int k = 0; k < FIN / 4; k++) row[k] = make_float4(0.f, 0.f, 0.f, 0.f);
}

// grid-wide generation barrier. All NB blocks are co-resident (grid==NB<=SMs).
__device__ __forceinline__ void gsync() {
    __syncthreads();
    if (threadIdx.x == 0) {
        __threadfence();                       // flush my block's writes
        unsigned gen = d_bar_gen;              // read BEFORE arriving
        if (atomicAdd(&d_bar_count, 1u) == NB - 1) {
            d_bar_count = 0;
            __threadfence();
            d_bar_gen = gen + 1;               // release
        } else {
            while (d_bar_gen == gen) __nanosleep(64);
        }
        __threadfence();                       // acquire
    }
    __syncthreads();
}

__device__ __forceinline__ int isout_f(int d, int N, unsigned G, unsigned long long m) {
    if (d == N - 1) return 1;
    return mdiv(((unsigned)d + 1u) * G, m) != mdiv((unsigned)d * G, m);
}

__device__ __forceinline__ void pass1_hit(int sj, int dj) {
    int p = atomicAdd(&d_nl2, 1);
    if (p < MAXL2) d_l2[p] = make_int2(sj, dj);
    unsigned bit = 1u << (sj & 31);
    unsigned old = atomicOr(&d_need_bits[sj >> 5], bit);
    if (!(old & bit)) {
        int s = atomicAdd(&d_nslots, 1);
        if (s < MAXSLOTS) { d_slot[sj] = s; d_slotnode[s] = sj; zero_row(s); }
    }
}

// ---------------------------------------------------------------------------
__global__ void __launch_bounds__(NT, 1)
k_mega(const float* __restrict__ x,
       const int* __restrict__ src, const int* __restrict__ dst,
       const int* __restrict__ batch,
       const float* __restrict__ W1, const float* __restrict__ b1,
       const float* __restrict__ W2, const float* __restrict__ b2,
       float* __restrict__ out,
       int N, int E, int G, unsigned long long m, int use_v4) {
    __shared__ unsigned sbits[NBW];            // 12.5 KB
    __shared__ float4   ysh[NT / 32][32];      // 16 KB, per-warp y rows

    const int gtid  = blockIdx.x * NT + threadIdx.x;
    const int gsize = NB * NT;
    const int lane  = threadIdx.x & 31;
    const int wib   = threadIdx.x >> 5;        // warp in block

    // ---- Phase A: out init, output-node marking, formula verification -----
    for (int i = gtid; i < G; i += gsize) out[i] = __ldg(&b2[0]);
    for (int i = gtid; i < N; i += gsize) {
        int bi = __ldg(&batch[i]);
        if (bi != mdiv((unsigned)i * (unsigned)G, m)) d_formula_ok = 0;
        bool last = (i == N - 1) || (bi != __ldg(&batch[i + 1]));
        if (last) {
            atomicOr(&d_isout_bits[i >> 5], 1u << (i & 31));
            atomicOr(&d_need_bits[i >> 5], 1u << (i & 31));
            int s = atomicAdd(&d_nslots, 1);
            if (s < MAXSLOTS) { d_slot[i] = s; d_slotnode[s] = i; zero_row(s); }
            int o = atomicAdd(&d_nout, 1);
            if (o < MAXSLOTS) d_outnodes[o] = i;
        }
    }
    gsync();

    // ---- Phase B: deg histogram + layer-2 edge collect + V1 extend --------
    {
        int use_f = d_formula_ok;
        if (use_v4) {
            const int4* dst4 = (const int4*)dst;
            int E4 = E >> 2;
            for (int j = gtid; j < E4; j += gsize) {
                int4 dd = __ldg(&dst4[j]);
                atomicAdd(&d_deg[dd.x], 1);
                atomicAdd(&d_deg[dd.y], 1);
                atomicAdd(&d_deg[dd.z], 1);
                atomicAdd(&d_deg[dd.w], 1);
                if (use_f) {
                    if (isout_f(dd.x, N, G, m)) pass1_hit(__ldg(&src[4*j+0]), dd.x);
                    if (isout_f(dd.y, N, G, m)) pass1_hit(__ldg(&src[4*j+1]), dd.y);
                    if (isout_f(dd.z, N, G, m)) pass1_hit(__ldg(&src[4*j+2]), dd.z);
                    if (isout_f(dd.w, N, G, m)) pass1_hit(__ldg(&src[4*j+3]), dd.w);
                } else {
                    if (test_bit(d_isout_bits, dd.x)) pass1_hit(__ldg(&src[4*j+0]), dd.x);
                    if (test_bit(d_isout_bits, dd.y)) pass1_hit(__ldg(&src[4*j+1]), dd.y);
                    if (test_bit(d_isout_bits, dd.z)) pass1_hit(__ldg(&src[4*j+2]), dd.z);
                    if (test_bit(d_isout_bits, dd.w)) pass1_hit(__ldg(&src[4*j+3]), dd.w);
                }
            }
            for (int j = (E4 << 2) + gtid; j < E; j += gsize) {
                int dj = __ldg(&dst[j]);
                atomicAdd(&d_deg[dj], 1);
                int hit = use_f ? isout_f(dj, N, G, m) : test_bit(d_isout_bits, dj);
                if (hit) pass1_hit(__ldg(&src[j]), dj);
            }
        } else {
            for (int j = gtid; j < E; j += gsize) {
                int dj = __ldg(&dst[j]);
                atomicAdd(&d_deg[dj], 1);
                int hit = use_f ? isout_f(dj, N, G, m) : test_bit(d_isout_bits, dj);
                if (hit) pass1_hit(__ldg(&src[j]), dj);
            }
        }
    }
    gsync();

    // ---- Phase C: scatter x[src]*dinv[src] into xagg[slot[dst]] -----------
    {
        for (int i = threadIdx.x; i < NBW; i += NT) sbits[i] = d_need_bits[i];
        __syncthreads();
        const float4* x4 = (const float4*)x;
        int wbase0 = gtid & ~31;               // warp-aligned start
        for (int base = wbase0; base < E; base += gsize) {
            int j = base + lane;
            bool in = j < E;
            int dj = 0, sj = 0, sl = 0, pred = 0;
            float w = 0.f;
            if (in) { dj = __ldg(&dst[j]); pred = (sbits[dj >> 5] >> (dj & 31)) & 1u; }
            if (pred) {
                sj = __ldg(&src[j]);
                sl = d_slot[dj];
                w  = rsqrtf((float)(__ldg(&d_deg[sj]) + 1));
            }
            unsigned mm = __ballot_sync(0xffffffffu, pred);
            while (mm) {
                int b = __ffs(mm) - 1;
                mm &= mm - 1;
                int   bs  = __shfl_sync(0xffffffffu, sj, b);
                int   bsl = __shfl_sync(0xffffffffu, sl, b);
                float bw  = __shfl_sync(0xffffffffu, w,  b);
                float4 xv = __ldg(&x4[(size_t)bs * (FIN / 4) + lane]);
                red_add_v4(&d_xagg[(size_t)bsl * FIN + lane * 4],
                           xv.x * bw, xv.y * bw, xv.z * bw, xv.w * bw);
            }
        }
    }
    gsync();

    // ---- Phase D: per-warp slot GEMV: tval = relu(y@W1+b1)@W2 -------------
    {
        int ns = d_nslots; if (ns > MAXSLOTS) ns = MAXSLOTS;
        int gw = gtid >> 5, nw = gsize >> 5;
        for (int s = gw; s < ns; s += nw) {
            int v = d_slotnode[s];
            float dv  = rsqrtf((float)(d_deg[v] + 1));
            float dv2 = dv * dv;
            float4 a = *(const float4*)&d_xagg[(size_t)s * FIN + 4 * lane];
            float4 b = __ldg((const float4*)&x[(size_t)v * FIN + 4 * lane]);
            float4 y;
            y.x = a.x * dv + b.x * dv2;
            y.y = a.y * dv + b.y * dv2;
            y.z = a.z * dv + b.z * dv2;
            y.w = a.w * dv + b.w * dv2;
            ysh[wib][lane] = y;
            __syncwarp();
            const float* yr = (const float*)ysh[wib];
            float h0 = __ldg(&b1[lane]), h1 = __ldg(&b1[lane + 32]);
            #pragma unroll 8
            for (int k = 0; k < FIN; k++) {
                float yk = yr[k];
                h0 = fmaf(yk, __ldg(&W1[k * HID + lane]),      h0);
                h1 = fmaf(yk, __ldg(&W1[k * HID + lane + 32]), h1);
            }
            float p = fmaxf(h0, 0.f) * __ldg(&W2[lane])
                    + fmaxf(h1, 0.f) * __ldg(&W2[lane + 32]);
            #pragma unroll
            for (int o = 16; o > 0; o >>= 1)
                p += __shfl_down_sync(0xffffffffu, p, o);
            if (lane == 0) { d_tval[s] = p; d_sdinv[s] = dv; }
            __syncwarp();
        }
    }
    gsync();

    // ---- Phase E: layer-2 edge reduce + self-loop terms into out ----------
    {
        int n1 = d_nl2;  if (n1 > MAXL2) n1 = MAXL2;
        int n2 = d_nout; if (n2 > MAXSLOTS) n2 = MAXSLOTS;
        for (int k = gtid; k < n1; k += gsize) {
            int2 e = d_l2[k];
            int ss = d_slot[e.x], sd = d_slot[e.y];
            atomicAdd(&out[__ldg(&batch[e.y])],
                      d_tval[ss] * d_sdinv[ss] * d_sdinv[sd]);
        }
        for (int k = gtid; k < n2; k += gsize) {
            int v  = d_outnodes[k];
            int sv = d_slot[v];
            float dv = d_sdinv[sv];
            atomicAdd(&out[__ldg(&batch[v])], d_tval[sv] * dv * dv);
        }
    }
    gsync();

    // ---- Phase F: reset scratch for the next (graph-replayed) call --------
    for (int i = gtid; i < MAXN; i += gsize) d_deg[i] = 0;
    for (int i = gtid; i < NBW; i += gsize) { d_isout_bits[i] = 0u; d_need_bits[i] = 0u; }
    if (gtid == 0) { d_nl2 = 0; d_nslots = 0; d_nout = 0; d_formula_ok = 1; }
}

// ---------------------------------------------------------------------------
extern "C" void kernel_launch(void* const* d_in, const int* in_sizes, int n_in,
                              void* d_out, int out_size) {
    const float* x     = (const float*)d_in[0];
    const int*   ei    = (const int*)  d_in[1];
    const int*   batch = (const int*)  d_in[2];
    const float* W1    = (const float*)d_in[3];
    const float* b1    = (const float*)d_in[4];
    const float* W2    = (const float*)d_in[5];
    const float* b2    = (const float*)d_in[6];
    float* out = (float*)d_out;

    const int N = in_sizes[2];
    const int E = in_sizes[1] / 2;
    const int G = out_size;

    const int* src = ei;
    const int* dst = ei + E;

    unsigned long long m = ((1ULL << MSHIFT) + (unsigned)N - 1) / (unsigned)N;
    int use_v4 = (((E & 3) == 0) && ((((uintptr_t)dst) & 15) == 0)) ? 1 : 0;

    k_mega<<<NB, NT>>>(x, src, dst, batch, W1, b1, W2, b2, out,
                       N, E, G, m, use_v4);
}

// round 12
// speedup vs baseline: 1.1584x; 1.1584x over previous
#include <cuda_runtime.h>
#include <stdint.h>
#include <math.h>

#define MAXN     100000
#define FIN      128
#define HID      64
#define NBW      ((MAXN + 31) / 32)   // 12.5 KB bitmaps
#define MAXSLOTS 16384                // |V1| bound (actual ~2.1k)
#define MAXL2    65536                // layer-2 edge bound (actual ~2k)
#define SBLOCKS  1184                 // scatter grid
#define STHREADS 256

// ---------------- static device scratch (zero at load; k_final re-zeroes) ---
__device__ int      d_deg[MAXN];
__device__ unsigned d_isout_bits[NBW];
__device__ unsigned d_need_bits[NBW];
__device__ int      d_slot[MAXN];
__device__ int      d_slotnode[MAXSLOTS];
__device__ __align__(16) float d_xagg[(size_t)MAXSLOTS * FIN];
__device__ float    d_tval[MAXSLOTS];
__device__ float    d_sdinv[MAXSLOTS];
__device__ int2     d_l2[MAXL2];
__device__ int      d_outnodes[MAXSLOTS];
__device__ int      d_nslots;
__device__ int      d_nl2;
__device__ int      d_nout;
__device__ int      d_formula_ok = 1;

__device__ __forceinline__ void red_add_v4(float* addr, float a, float b, float c, float d) {
    asm volatile("red.global.add.v4.f32 [%0], {%1,%2,%3,%4};"
                 :: "l"(addr), "f"(a), "f"(b), "f"(c), "f"(d) : "memory");
}
__device__ __forceinline__ int test_bit(const unsigned* bits, int i) {
    return (bits[i >> 5] >> (i & 31)) & 1u;
}
__device__ __forceinline__ void zero_row(int s) {
    float4* row = (float4*)&d_xagg[(size_t)s * FIN];
    #pragma unroll
    for (int k = 0; k < FIN / 4; k++) row[k] = make_float4(0.f, 0.f, 0.f, 0.f);
}
// outputs satisfy (d mod P) ∈ {R0,R1}; q=floor(d/P) by magic (exact, host-checked)
__device__ __forceinline__ int isout_r(int d, unsigned P, unsigned M,
                                       unsigned R0, unsigned R1) {
    unsigned q = __umulhi((unsigned)d, M);
    unsigned r = (unsigned)d - q * P;
    return (r == R0) | (r == R1);
}

// ---------------------------------------------------------------------------
// K1: out init; mark outputs (last of each graph); verify residue hypothesis.
__global__ void k_mark(const int* __restrict__ batch, int N,
                       float* __restrict__ out, const float* __restrict__ b2, int G,
                       unsigned P, unsigned M, unsigned R0, unsigned R1, int host_ok) {
    int i = blockIdx.x * blockDim.x + threadIdx.x;
    if (i < G) out[i] = __ldg(&b2[0]);
    if (i == 0 && !host_ok) d_formula_ok = 0;
    if (i >= N) return;
    bool last = (i == N - 1) || (__ldg(&batch[i]) != __ldg(&batch[i + 1]));
    if (host_ok && ((isout_r(i, P, M, R0, R1) != 0) != last))
        d_formula_ok = 0;                           // any mismatch kills fast path
    if (last) {
        atomicOr(&d_isout_bits[i >> 5], 1u << (i & 31));
        atomicOr(&d_need_bits[i >> 5], 1u << (i & 31));
        int s = atomicAdd(&d_nslots, 1);
        if (s < MAXSLOTS) { d_slot[i] = s; d_slotnode[s] = i; zero_row(s); }
        int o = atomicAdd(&d_nout, 1);
        if (o < MAXSLOTS) d_outnodes[o] = i;
    }
}

// K2: FUSED deg histogram (RED) + layer-2 edge collect + V1 slot set.
__device__ __forceinline__ void scan1_hit(int sj, int dj) {
    int p = atomicAdd(&d_nl2, 1);
    if (p < MAXL2) d_l2[p] = make_int2(sj, dj);
    unsigned bit = 1u << (sj & 31);
    unsigned old = atomicOr(&d_need_bits[sj >> 5], bit);
    if (!(old & bit)) {
        int s = atomicAdd(&d_nslots, 1);
        if (s < MAXSLOTS) { d_slot[sj] = s; d_slotnode[s] = sj; zero_row(s); }
    }
}

__global__ void k_scan1_v4(const int* __restrict__ src, const int4* __restrict__ dst4,
                           int E4, int E, unsigned P, unsigned M,
                           unsigned R0, unsigned R1) {
    int j = blockIdx.x * blockDim.x + threadIdx.x;
    int use_f = d_formula_ok;
    if (j < E4) {
        int4 dd = __ldg(&dst4[j]);
        atomicAdd(&d_deg[dd.x], 1);
        atomicAdd(&d_deg[dd.y], 1);
        atomicAdd(&d_deg[dd.z], 1);
        atomicAdd(&d_deg[dd.w], 1);
        if (use_f) {    // 5-instr ALU output test
            if (isout_r(dd.x, P, M, R0, R1)) scan1_hit(__ldg(&src[4*j+0]), dd.x);
            if (isout_r(dd.y, P, M, R0, R1)) scan1_hit(__ldg(&src[4*j+1]), dd.y);
            if (isout_r(dd.z, P, M, R0, R1)) scan1_hit(__ldg(&src[4*j+2]), dd.z);
            if (isout_r(dd.w, P, M, R0, R1)) scan1_hit(__ldg(&src[4*j+3]), dd.w);
        } else {        // fallback: bitmap probe
            if (test_bit(d_isout_bits, dd.x)) scan1_hit(__ldg(&src[4*j+0]), dd.x);
            if (test_bit(d_isout_bits, dd.y)) scan1_hit(__ldg(&src[4*j+1]), dd.y);
            if (test_bit(d_isout_bits, dd.z)) scan1_hit(__ldg(&src[4*j+2]), dd.z);
            if (test_bit(d_isout_bits, dd.w)) scan1_hit(__ldg(&src[4*j+3]), dd.w);
        }
    }
    int tbase = E4 * 4;
    if (j < E - tbase) {          // tail (<4 edges)
        const int* dst = (const int*)dst4;
        int dj = __ldg(&dst[tbase + j]);
        atomicAdd(&d_deg[dj], 1);
        int hit = use_f ? isout_r(dj, P, M, R0, R1) : test_bit(d_isout_bits, dj);
        if (hit) scan1_hit(__ldg(&src[tbase + j]), dj);
    }
}
__global__ void k_scan1_s(const int* __restrict__ src, const int* __restrict__ dst,
                          int E, unsigned P, unsigned M, unsigned R0, unsigned R1) {
    int i = blockIdx.x * blockDim.x + threadIdx.x;
    if (i >= E) return;
    int dj = __ldg(&dst[i]);
    atomicAdd(&d_deg[dj], 1);
    int hit = d_formula_ok ? isout_r(dj, P, M, R0, R1) : test_bit(d_isout_bits, dj);
    if (hit) scan1_hit(__ldg(&src[i]), dj);
}

// K3: scatter x[src]*rsqrt(deg[src]+1) into xagg[slot[dst]] for dst in V1.
// need-bitmap staged in smem; 1184 blocks -> ~2.6 int4 iters/thread.
__global__ void __launch_bounds__(STHREADS) k_scatter(
        const int* __restrict__ src, const int* __restrict__ dst,
        const float4* __restrict__ x4, int E4, int E) {
    __shared__ unsigned sb[NBW];
    for (int i = threadIdx.x; i < NBW; i += STHREADS) sb[i] = d_need_bits[i];
    __syncthreads();
    const int4* dst4 = (const int4*)dst;
    int lane   = threadIdx.x & 31;
    int wglob  = (blockIdx.x * blockDim.x + threadIdx.x) >> 5;
    int nwarps = (gridDim.x * blockDim.x) >> 5;
    for (int base = wglob * 32; base < E4; base += nwarps * 32) {
        int j = base + lane;
        bool in = j < E4;
        int4 dd = make_int4(0, 0, 0, 0);
        if (in) dd = __ldg(&dst4[j]);
        #pragma unroll
        for (int c = 0; c < 4; c++) {
            int dj = (c == 0) ? dd.x : (c == 1) ? dd.y : (c == 2) ? dd.z : dd.w;
            int pred = in && ((sb[dj >> 5] >> (dj & 31)) & 1u);
            int sj = 0, sl = 0;
            float w = 0.f;
            if (pred) {
                sj = __ldg(&src[4 * j + c]);
                sl = d_slot[dj];
                w  = rsqrtf((float)(__ldg(&d_deg[sj]) + 1));
            }
            unsigned mm = __ballot_sync(0xffffffffu, pred);
            while (mm) {
                int b = __ffs(mm) - 1;
                mm &= mm - 1;
                int   bs  = __shfl_sync(0xffffffffu, sj, b);
                int   bsl = __shfl_sync(0xffffffffu, sl, b);
                float bw  = __shfl_sync(0xffffffffu, w,  b);
                float4 xv = __ldg(&x4[(size_t)bs * (FIN / 4) + lane]);
                red_add_v4(&d_xagg[(size_t)bsl * FIN + lane * 4],
                           xv.x * bw, xv.y * bw, xv.z * bw, xv.w * bw);
            }
        }
    }
    // tail edges (<4): handled scalar by first threads of block 0, no ballot
    int tbase = E4 * 4;
    int t = blockIdx.x * blockDim.x + threadIdx.x;
    if (t < E - tbase) {
        int j  = tbase + t;
        int dj = __ldg(&dst[j]);
        if ((sb[dj >> 5] >> (dj & 31)) & 1u) {
            int sj = __ldg(&src[j]);
            int sl = d_slot[dj];
            float w = rsqrtf((float)(__ldg(&d_deg[sj]) + 1));
            for (int k = 0; k < 32; k++) {
                float4 xv = __ldg(&x4[(size_t)sj * (FIN / 4) + k]);
                red_add_v4(&d_xagg[(size_t)sl * FIN + k * 4],
                           xv.x * w, xv.y * w, xv.z * w, xv.w * w);
            }
        }
    }
}

// K4: per V1 node: y = xagg*dv + x*dv^2; h1 = relu(y@W1+b1); tval = h1@W2.
__global__ void k_compute(const float* __restrict__ x,
                          const float* __restrict__ W1,
                          const float* __restrict__ b1,
                          const float* __restrict__ W2) {
    __shared__ float ysh[FIN];
    __shared__ float redsh[HID];
    int ns = d_nslots; if (ns > MAXSLOTS) ns = MAXSLOTS;
    int t  = threadIdx.x;   // 0..63
    for (int s = blockIdx.x; s < ns; s += gridDim.x) {
        int v = d_slotnode[s];
        float dv  = rsqrtf((float)(d_deg[v] + 1));
        float dv2 = dv * dv;
        #pragma unroll
        for (int k = t; k < FIN; k += HID)
            ysh[k] = d_xagg[(size_t)s * FIN + k] * dv + x[(size_t)v * FIN + k] * dv2;
        __syncthreads();
        float acc = 0.f;
        #pragma unroll 16
        for (int k = 0; k < FIN; k++)
            acc = fmaf(ysh[k], W1[k * HID + t], acc);
        float h = fmaxf(acc + b1[t], 0.f);
        redsh[t] = h * W2[t];
        __syncthreads();
        if (t < 32) {
            float p = redsh[t] + redsh[t + 32];
            #pragma unroll
            for (int o = 16; o > 0; o >>= 1)
                p += __shfl_down_sync(0xffffffffu, p, o);
            if (t == 0) { d_tval[s] = p; d_sdinv[s] = dv; }
        }
        __syncthreads();
    }
}

// K5: layer-2 reduce + self-loops + zero scratch for next call
__global__ void k_final(const int* __restrict__ batch, float* __restrict__ out) {
    int i = blockIdx.x * blockDim.x + threadIdx.x;
    if (blockIdx.x == 0) {
        int n1 = d_nl2; if (n1 > MAXL2) n1 = MAXL2;
        for (int k = threadIdx.x; k < n1; k += blockDim.x) {
            int2 e = d_l2[k];
            int ss = d_slot[e.x], sd = d_slot[e.y];
            atomicAdd(&out[__ldg(&batch[e.y])], d_tval[ss] * d_sdinv[ss] * d_sdinv[sd]);
        }
        __syncthreads();
        if (threadIdx.x == 0) d_nl2 = 0;
    } else if (blockIdx.x == 1) {
        int n2 = d_nout; if (n2 > MAXSLOTS) n2 = MAXSLOTS;
        for (int k = threadIdx.x; k < n2; k += blockDim.x) {
            int v  = d_outnodes[k];
            int sv = d_slot[v];
            float dv = d_sdinv[sv];
            atomicAdd(&out[__ldg(&batch[v])], d_tval[sv] * dv * dv);
        }
        __syncthreads();
        if (threadIdx.x == 0) { d_nout = 0; d_nslots = 0; d_formula_ok = 1; }
    }
    if (i < MAXN) d_deg[i] = 0;
    if (i < NBW) { d_isout_bits[i] = 0u; d_need_bits[i] = 0u; }
}

// ---------------------------------------------------------------------------
static unsigned host_gcd(unsigned a, unsigned b) {
    while (b) { unsigned t = a % b; a = b; b = t; }
    return a;
}

extern "C" void kernel_launch(void* const* d_in, const int* in_sizes, int n_in,
                              void* d_out, int out_size) {
    const float* x     = (const float*)d_in[0];
    const int*   ei    = (const int*)  d_in[1];
    const int*   batch = (const int*)  d_in[2];
    const float* W1    = (const float*)d_in[3];
    const float* b1    = (const float*)d_in[4];
    const float* W2    = (const float*)d_in[5];
    const float* b2    = (const float*)d_in[6];
    float* out = (float*)d_out;

    const int N = in_sizes[2];
    const int E = in_sizes[1] / 2;
    const int G = out_size;

    const int* src = ei;
    const int* dst = ei + E;

    // Residue hypothesis: batch[i] = (i*G)//N  =>  outputs at (i mod P) in {R0,R1}
    unsigned g0 = host_gcd((unsigned)N, (unsigned)G);
    unsigned P  = (unsigned)N / g0;
    unsigned per_period = (unsigned)G / g0;         // outputs per period
    unsigned M  = (unsigned)(((1ULL << 32) + P - 1) / P);
    unsigned long long err = (unsigned long long)M * P - (1ULL << 32);
    int exact = (err == 0) || ((unsigned long long)N <= (1ULL << 32) / (err ? err : 1));
    unsigned R0 = 0, R1 = 0;
    int host_ok = 0;
    if (exact && (per_period == 1 || per_period == 2) && G >= 1) {
        R0 = (unsigned)((((unsigned long long)N      - 1) / G) % P);
        R1 = (per_period == 2)
           ? (unsigned)(((2ULL * (unsigned long long)N - 1) / G) % P) : R0;
        host_ok = 1;
    }

    int gN = (N + 255) / 256;
    k_mark<<<gN, 256>>>(batch, N, out, b2, G, P, M, R0, R1, host_ok);

    bool vec_ok = ((((uintptr_t)src) & 15) == 0) && ((((uintptr_t)dst) & 15) == 0);
    int E4 = E / 4;
    if (vec_ok) {
        k_scan1_v4<<<(E4 + 255) / 256, 256>>>(src, (const int4*)dst, E4, E, P, M, R0, R1);
        k_scatter <<<SBLOCKS, STHREADS>>>(src, dst, (const float4*)x, E4, E);
    } else {
        k_scan1_s<<<(E + 255) / 256, 256>>>(src, dst, E, P, M, R0, R1);
        k_scatter<<<SBLOCKS, STHREADS>>>(src, dst, (const float4*)x, 0, E);
    }

    k_compute<<<592, HID>>>(x, W1, b1, W2);
    k_final  <<<gN, 256>>>(batch, out);
}

// round 13
// speedup vs baseline: 1.4165x; 1.2227x over previous
#include <cuda_runtime.h>
#include <stdint.h>
#include <math.h>

// Problem constants (fixed by dataset)
#define MAXN 100000
#define MAXE 3200000
#define FIN  128
#define HID  64
#define NBW  ((MAXN + 31) / 32)   // bitmap words

// ---------------- static device scratch (no dynamic allocation) -------------
__device__ int      d_deg[MAXN];
__device__ float    d_dinv[MAXN];
__device__ unsigned d_isout_bits[NBW];   // 12.5 KB
__device__ unsigned d_need_bits[NBW];    // 12.5 KB
__device__ int      d_slot[MAXN];        // node -> compact slot (valid iff needed)
__device__ int      d_slotnode[MAXN];    // slot -> node
__device__ __align__(16) float d_xagg[(size_t)MAXN * FIN];
__device__ float    d_tval[MAXN];        // per-slot scalar t = relu(h1)@W2
__device__ int2     d_l2[MAXE];          // edges whose dst is an output node
__device__ int      d_outnodes[MAXN];
__device__ int      d_nslots;
__device__ int      d_nl2;
__device__ int      d_nout;

__device__ __forceinline__ void red_add_v4(float* addr, float a, float b, float c, float d) {
    asm volatile("red.global.add.v4.f32 [%0], {%1,%2,%3,%4};"
                 :: "l"(addr), "f"(a), "f"(b), "f"(c), "f"(d) : "memory");
}

__device__ __forceinline__ int test_bit(const unsigned* bits, int i) {
    return (bits[i >> 5] >> (i & 31)) & 1u;
}

// ---------------------------------------------------------------------------
__global__ void k_init(int N) {
    int i = blockIdx.x * blockDim.x + threadIdx.x;
    if (i < N) d_deg[i] = 0;
    if (i < NBW) { d_isout_bits[i] = 0u; d_need_bits[i] = 0u; }
    if (i == 0) { d_nslots = 0; d_nl2 = 0; d_nout = 0; }
}

// output nodes (last of each graph in sorted batch); also init out[] with bias
__global__ void k_mark(const int* __restrict__ batch, int N,
                       float* __restrict__ out, const float* __restrict__ b2, int G) {
    int i = blockIdx.x * blockDim.x + threadIdx.x;
    if (i < G) out[i] = b2[0];
    if (i >= N) return;
    bool last = (i == N - 1) || (batch[i] != batch[i + 1]);
    if (last) {
        atomicOr(&d_isout_bits[i >> 5], 1u << (i & 31));
        atomicOr(&d_need_bits[i >> 5], 1u << (i & 31));
        int o = atomicAdd(&d_nout, 1);
        d_outnodes[o] = i;
    }
}

__device__ __forceinline__ void pass1_one(int sj, int dj) {
    atomicAdd(&d_deg[dj], 1);
    if (test_bit(d_isout_bits, dj)) {
        int p = atomicAdd(&d_nl2, 1);
        d_l2[p] = make_int2(sj, dj);
        atomicOr(&d_need_bits[sj >> 5], 1u << (sj & 31));
    }
}

// fused: in-degree histogram + layer-2 edge collection, 4 edges/thread
__global__ void k_pass1_v4(const int4* __restrict__ src4, const int4* __restrict__ dst4, int E4) {
    int i = blockIdx.x * blockDim.x + threadIdx.x;
    if (i >= E4) return;
    int4 s = __ldg(&src4[i]);
    int4 d = __ldg(&dst4[i]);
    pass1_one(s.x, d.x);
    pass1_one(s.y, d.y);
    pass1_one(s.z, d.z);
    pass1_one(s.w, d.w);
}
// scalar fallback
__global__ void k_pass1_s(const int* __restrict__ src, const int* __restrict__ dst, int E) {
    int i = blockIdx.x * blockDim.x + threadIdx.x;
    if (i >= E) return;
    pass1_one(__ldg(&src[i]), __ldg(&dst[i]));
}

// dinv for all nodes; slot + xagg zero for needed nodes
__global__ void k_slots(int N) {
    int i = blockIdx.x * blockDim.x + threadIdx.x;
    if (i >= N) return;
    d_dinv[i] = rsqrtf((float)(d_deg[i] + 1));
    if (test_bit(d_need_bits, i)) {
        int s = atomicAdd(&d_nslots, 1);
        d_slot[i] = s;
        d_slotnode[s] = i;
        float4* row = (float4*)&d_xagg[(size_t)s * FIN];
        #pragma unroll
        for (int k = 0; k < FIN / 4; k++) row[k] = make_float4(0.f, 0.f, 0.f, 0.f);
    }
}

// scan all edges (int4: 4 edges/thread); edges into needed nodes ->
// warp-cooperative red.v4 scatter of x[src]*dinv[src] into xagg[slot[dst]]
__global__ void k_gather_v4(const int* __restrict__ src, const int4* __restrict__ dst4,
                            const float4* __restrict__ x4, int E4) {
    int idx  = blockIdx.x * blockDim.x + threadIdx.x;
    int lane = threadIdx.x & 31;
    bool in = idx < E4;
    int4 dd = make_int4(0, 0, 0, 0);
    if (in) dd = __ldg(&dst4[idx]);
    #pragma unroll
    for (int c = 0; c < 4; c++) {
        int d = (c == 0) ? dd.x : (c == 1) ? dd.y : (c == 2) ? dd.z : dd.w;
        int pred = in && test_bit(d_need_bits, d);   // 12.5 KB bitmap: L1 hit
        int s = 0;
        if (pred) s = __ldg(&src[4 * idx + c]);
        unsigned mask = __ballot_sync(0xffffffffu, pred);
        while (mask) {
            int b = __ffs(mask) - 1;
            mask &= mask - 1;
            int bs = __shfl_sync(0xffffffffu, s, b);
            int bd = __shfl_sync(0xffffffffu, d, b);
            int sl = d_slot[bd];
            float w = d_dinv[bs];
            float4 xv = __ldg(&x4[(size_t)bs * (FIN / 4) + lane]);
            red_add_v4(&d_xagg[(size_t)sl * FIN + lane * 4],
                       xv.x * w, xv.y * w, xv.z * w, xv.w * w);
        }
    }
}
// scalar fallback
__global__ void k_gather_s(const int* __restrict__ src, const int* __restrict__ dst,
                           const float4* __restrict__ x4, int E) {
    int idx  = blockIdx.x * blockDim.x + threadIdx.x;
    int lane = threadIdx.x & 31;
    int s = 0, d = 0, pred = 0;
    if (idx < E) {
        d = __ldg(&dst[idx]);
        pred = test_bit(d_need_bits, d);
        if (pred) s = __ldg(&src[idx]);
    }
    unsigned mask = __ballot_sync(0xffffffffu, pred);
    while (mask) {
        int b = __ffs(mask) - 1;
        mask &= mask - 1;
        int bs = __shfl_sync(0xffffffffu, s, b);
        int bd = __shfl_sync(0xffffffffu, d, b);
        int sl = d_slot[bd];
        float w = d_dinv[bs];
        float4 xv = __ldg(&x4[(size_t)bs * (FIN / 4) + lane]);
        red_add_v4(&d_xagg[(size_t)sl * FIN + lane * 4],
                   xv.x * w, xv.y * w, xv.z * w, xv.w * w);
    }
}

// per needed node: y = xagg*dinv + x*dinv^2 ; h1 = relu(y@W1+b1) ; t = h1@W2
__global__ void k_compute(const float* __restrict__ x,
                          const float* __restrict__ W1,
                          const float* __restrict__ b1,
                          const float* __restrict__ W2) {
    __shared__ float ysh[FIN];
    __shared__ float redsh[HID];
    int ns = d_nslots;
    int t  = threadIdx.x;   // 0..63
    for (int s = blockIdx.x; s < ns; s += gridDim.x) {
        int v = d_slotnode[s];
        float dv  = d_dinv[v];
        float dv2 = dv * dv;
        #pragma unroll
        for (int k = t; k < FIN; k += HID)
            ysh[k] = d_xagg[(size_t)s * FIN + k] * dv + x[(size_t)v * FIN + k] * dv2;
        __syncthreads();
        float acc = 0.f;
        #pragma unroll 16
        for (int k = 0; k < FIN; k++)
            acc = fmaf(ysh[k], W1[k * HID + t], acc);
        float h = fmaxf(acc + b1[t], 0.f);
        redsh[t] = h * W2[t];
        __syncthreads();
        if (t < 32) {
            float p = redsh[t] + redsh[t + 32];
            #pragma unroll
            for (int o = 16; o > 0; o >>= 1)
                p += __shfl_down_sync(0xffffffffu, p, o);
            if (t == 0) d_tval[s] = p;
        }
        __syncthreads();
    }
}

// layer-2 edge aggregation + self-loop terms into the G outputs
__global__ void k_final(const int* __restrict__ batch, float* __restrict__ out) {
    int n1 = d_nl2, n2 = d_nout;
    int stride = gridDim.x * blockDim.x;
    for (int i = blockIdx.x * blockDim.x + threadIdx.x; i < n1; i += stride) {
        int2 e = d_l2[i];
        float val = d_tval[d_slot[e.x]] * d_dinv[e.x] * d_dinv[e.y];
        atomicAdd(&out[batch[e.y]], val);
    }
    for (int i = blockIdx.x * blockDim.x + threadIdx.x; i < n2; i += stride) {
        int v = d_outnodes[i];
        float dv = d_dinv[v];
        atomicAdd(&out[batch[v]], d_tval[d_slot[v]] * dv * dv);
    }
}

// ---------------------------------------------------------------------------
extern "C" void kernel_launch(void* const* d_in, const int* in_sizes, int n_in,
                              void* d_out, int out_size) {
    const float* x     = (const float*)d_in[0];
    const int*   ei    = (const int*)  d_in[1];
    const int*   batch = (const int*)  d_in[2];
    const float* W1    = (const float*)d_in[3];
    const float* b1    = (const float*)d_in[4];
    const float* W2    = (const float*)d_in[5];
    const float* b2    = (const float*)d_in[6];
    float* out = (float*)d_out;

    const int N = in_sizes[2];
    const int E = in_sizes[1] / 2;
    const int G = out_size;

    const int* src = ei;
    const int* dst = ei + E;

    int gN = (N + 255) / 256;

    k_init<<<gN, 256>>>(N);
    k_mark<<<gN, 256>>>(batch, N, out, b2, G);

    bool vec_ok = ((E & 3) == 0) &&
                  ((((uintptr_t)src) & 15) == 0) && ((((uintptr_t)dst) & 15) == 0);
    if (vec_ok) {
        int E4 = E / 4;
        int gE4 = (E4 + 255) / 256;
        k_pass1_v4 <<<gE4, 256>>>((const int4*)src, (const int4*)dst, E4);
        k_slots    <<<gN, 256>>>(N);
        k_gather_v4<<<gE4, 256>>>(src, (const int4*)dst, (const float4*)x, E4);
    } else {
        int gE = (E + 255) / 256;
        k_pass1_s <<<gE, 256>>>(src, dst, E);
        k_slots   <<<gN, 256>>>(N);
        k_gather_s<<<gE, 256>>>(src, dst, (const float4*)x, E);
    }

    k_compute<<<2048, HID>>>(x, W1, b1, W2);
    k_final  <<<64, 256>>>(batch, out);
}